// round 14
// baseline (speedup 1.0000x reference)
#include <cuda_runtime.h>
#include <cuda_bf16.h>
#include <math.h>
#include <stdint.h>

#define NV   50257
#define NPAD 50304          // 393 * 128
#define DD   128
#define BB_  2048
#define CC   10

typedef unsigned long long u64;

// ---------------- scratch (static __device__ — allocation-free) ----------------
__device__ __align__(16) __nv_bfloat16 g_zb[BB_ * DD];    // z in bf16
__device__ float g_S[BB_];                                // sum exp(logits) per row
__device__ float g_R[BB_];                                // sum of picked logits per row
__device__ float g_kl[BB_];

// ---------------- common helpers ----------------
__device__ __forceinline__ uint32_t smem_to_u32(const void* p) {
    uint32_t a;
    asm("{ .reg .u64 t; cvta.to.shared.u64 t, %1; cvt.u32.u64 %0, t; }"
        : "=r"(a) : "l"(p));
    return a;
}
__device__ __forceinline__ float softplusf(float x) {
    return fmaxf(x, 0.f) + log1pf(expf(-fabsf(x)));
}
__device__ __forceinline__ void mma16816(float c[4], const uint32_t a[4],
                                         uint32_t b0, uint32_t b1) {
    asm volatile(
        "mma.sync.aligned.m16n8k16.row.col.f32.bf16.bf16.f32 "
        "{%0,%1,%2,%3},{%4,%5,%6,%7},{%8,%9},{%0,%1,%2,%3};\n"
        : "+f"(c[0]), "+f"(c[1]), "+f"(c[2]), "+f"(c[3])
        : "r"(a[0]), "r"(a[1]), "r"(a[2]), "r"(a[3]), "r"(b0), "r"(b1));
}
__device__ __forceinline__ void ldmatrix_x4(uint32_t r[4], uint32_t addr) {
    asm volatile("ldmatrix.sync.aligned.m8n8.x4.shared.b16 {%0,%1,%2,%3}, [%4];"
        : "=r"(r[0]), "=r"(r[1]), "=r"(r[2]), "=r"(r[3]) : "r"(addr));
}
__device__ __forceinline__ uint4 f8_to_bf16x8(float4 f0, float4 f1) {
    __nv_bfloat162 h0 = __floats2bfloat162_rn(f0.x, f0.y);
    __nv_bfloat162 h1 = __floats2bfloat162_rn(f0.z, f0.w);
    __nv_bfloat162 h2 = __floats2bfloat162_rn(f1.x, f1.y);
    __nv_bfloat162 h3 = __floats2bfloat162_rn(f1.z, f1.w);
    return make_uint4(*(uint32_t*)&h0, *(uint32_t*)&h1,
                      *(uint32_t*)&h2, *(uint32_t*)&h3);
}

// ---------------- kernel 1: inference net (tensor-core affine) ----------------
#define ALD   264
#define BLD   264
#define HLD   136
#define W2LD  136        // bf16 Wmu/Wsig row stride
#define OFF_A 0
#define OFF_B 101376
#define OFF_H 168960
#define SMEM_INF 221184
#define OFF_HS 135168
#define OFF_SG 143360
#define OFF_Z  151552

__global__ void __launch_bounds__(512) k_infnet(
    const int* __restrict__ x_batch, const int* __restrict__ ctx,
    const float* __restrict__ eps, const float* __restrict__ inf_emb,
    const float* __restrict__ W_aff, const float* __restrict__ b_aff,
    const float* __restrict__ W_mu,  const float* __restrict__ b_mu,
    const float* __restrict__ W_sig, const float* __restrict__ b_sig,
    const float* __restrict__ gen_sigma_emb,
    const float* __restrict__ W_gen, const float* __restrict__ b_gen)
{
    extern __shared__ __align__(16) char smx[];
    __nv_bfloat16* A  = (__nv_bfloat16*)(smx + OFF_A);
    __nv_bfloat16* Bm = (__nv_bfloat16*)(smx + OFF_B);
    __nv_bfloat16* H  = (__nv_bfloat16*)(smx + OFF_H);
    const uint32_t sb = smem_to_u32(smx);

    const int tid  = threadIdx.x;
    const int w    = tid >> 5;
    const int lane = tid & 31;
    const int b0   = blockIdx.x * 16;

    if (tid < 16) { g_S[b0 + tid] = 0.f; g_R[b0 + tid] = 0.f; }

    const uint4 z4 = make_uint4(0u, 0u, 0u, 0u);

    // stage B = W_aff [128 d][256 e] fp32 -> bf16
    for (int idx = tid; idx < 128 * 32; idx += 512) {
        int d = idx >> 5, g8 = idx & 31;
        const float4* src = (const float4*)(W_aff + (size_t)d * 256 + g8 * 8);
        *(uint4*)(Bm + d * BLD + g8 * 8) = f8_to_bf16x8(src[0], src[1]);
    }
    if (tid < 128) *(uint4*)(Bm + tid * BLD + 256) = z4;

    // stage A rows: r = b*10+c ; cols 0..127 = center_b, 128..255 = ctx_{b,c}
    for (int idx = tid; idx < 5120; idx += 512) {
        int r = idx >> 5, g8 = idx & 31;
        int b = r / 10, c = r - b * 10;
        int bg = b0 + b;
        int word = (g8 < 16) ? x_batch[bg] : ctx[bg * CC + c];
        const float4* src = (const float4*)(inf_emb + (size_t)word * DD + (g8 & 15) * 8);
        *(uint4*)(A + r * ALD + g8 * 8) = f8_to_bf16x8(src[0], src[1]);
    }
    if (tid < 160) *(uint4*)(A + tid * ALD + 256) = z4;
    for (int idx = tid; idx < 32 * 33; idx += 512) {
        int r = 160 + idx / 33, gc = idx % 33;
        *(uint4*)(A + r * ALD + gc * 8) = z4;
    }
    __syncthreads();

    // ---- GEMM: 16 warps, warp tile M=48 x N=32, K=256 ----
    const int wm = w & 3, wn = w >> 2;
    const uint32_t aBase = sb + OFF_A +
        (uint32_t)(((wm * 48 + (lane & 15)) * ALD + ((lane & 16) >> 1)) * 2);
    uint32_t bB[2];
#pragma unroll
    for (int np = 0; np < 2; np++)
        bB[np] = sb + OFF_B +
            (uint32_t)(((wn * 32 + np * 16 + ((lane & 16) >> 1) + (lane & 7)) * BLD
                        + (lane & 8)) * 2);

    float acc[3][4][4];
#pragma unroll
    for (int mi = 0; mi < 3; mi++)
#pragma unroll
        for (int nj = 0; nj < 4; nj++)
#pragma unroll
            for (int q = 0; q < 4; q++) acc[mi][nj][q] = 0.f;

#pragma unroll 4
    for (int kk = 0; kk < 16; kk++) {
        const uint32_t kb = (uint32_t)(kk * 32);
        uint32_t am[3][4];
#pragma unroll
        for (int mi = 0; mi < 3; mi++)
            ldmatrix_x4(am[mi], aBase + (uint32_t)(mi * 16 * ALD * 2) + kb);
#pragma unroll
        for (int np = 0; np < 2; np++) {
            uint32_t bq[4];
            ldmatrix_x4(bq, bB[np] + kb);
#pragma unroll
            for (int mi = 0; mi < 3; mi++) {
                mma16816(acc[mi][2 * np],     am[mi], bq[0], bq[1]);
                mma16816(acc[mi][2 * np + 1], am[mi], bq[2], bq[3]);
            }
        }
    }

    // epilogue: + b_aff, ReLU, store h (bf16)
    {
        const int g = lane >> 2, t = lane & 3;
        float2 bav[4];
#pragma unroll
        for (int nj = 0; nj < 4; nj++)
            bav[nj] = *(const float2*)(b_aff + wn * 32 + nj * 8 + 2 * t);
#pragma unroll
        for (int mi = 0; mi < 3; mi++) {
            int row = wm * 48 + mi * 16 + g;
#pragma unroll
            for (int nj = 0; nj < 4; nj++) {
                int col = wn * 32 + nj * 8 + 2 * t;
                float v0 = fmaxf(acc[mi][nj][0] + bav[nj].x, 0.f);
                float v1 = fmaxf(acc[mi][nj][1] + bav[nj].y, 0.f);
                float v2 = fmaxf(acc[mi][nj][2] + bav[nj].x, 0.f);
                float v3 = fmaxf(acc[mi][nj][3] + bav[nj].y, 0.f);
                *(__nv_bfloat162*)(H + row * HLD + col) = __floats2bfloat162_rn(v0, v1);
                *(__nv_bfloat162*)(H + (row + 8) * HLD + col) = __floats2bfloat162_rn(v2, v3);
            }
        }
    }
    __syncthreads();   // A/B dead; H ready

    __nv_bfloat16* Wt2h = (__nv_bfloat16*)smx;   // [256][136] bf16
    float* hsm = (float*)(smx + OFF_HS);
    float* sgb = (float*)(smx + OFF_SG);
    float* zsm = (float*)(smx + OFF_Z);
    const int d0 = lane * 4;

    // hsum: warp w owns batch w
    {
        int b = w;
        float s0 = 0.f, s1 = 0.f, s2 = 0.f, s3 = 0.f;
#pragma unroll
        for (int c = 0; c < CC; c++) {
            const __nv_bfloat162* hp = (const __nv_bfloat162*)(H + (b * 10 + c) * HLD + d0);
            float2 p0 = __bfloat1622float2(hp[0]);
            float2 p1 = __bfloat1622float2(hp[1]);
            s0 += p0.x; s1 += p0.y; s2 += p1.x; s3 += p1.y;
        }
        *(float4*)(hsm + b * 128 + d0) = make_float4(s0, s1, s2, s3);
    }
    // stage W_mu^T / W_sig^T -> bf16
    for (int idx = tid; idx < 128 * 128; idx += 512) {
        int d = idx >> 7, k = idx & 127;
        Wt2h[k * W2LD + d]         = __float2bfloat16(W_mu[idx]);
        Wt2h[(128 + k) * W2LD + d] = __float2bfloat16(W_sig[idx]);
    }
    __syncthreads();

    // GEMV: warps wh==0 -> mu, wh==1 -> sig; warp handles batches {wq, wq+8}
    const int wh = w >> 3, wq = w & 7;
    int bL[2] = {wq, wq + 8};
    float4 bias4 = wh ? *(const float4*)(b_sig + d0) : *(const float4*)(b_mu + d0);
    float a4[2][4];
#pragma unroll
    for (int bb = 0; bb < 2; bb++) {
        a4[bb][0] = bias4.x; a4[bb][1] = bias4.y;
        a4[bb][2] = bias4.z; a4[bb][3] = bias4.w;
    }
    const int kr0 = wh * 128;
    for (int k4 = 0; k4 < 128; k4 += 4) {
        float hv[2][4];
#pragma unroll
        for (int bb = 0; bb < 2; bb++)
            *(float4*)hv[bb] = *(const float4*)(hsm + bL[bb] * 128 + k4);
#pragma unroll
        for (int q = 0; q < 4; q++) {
            const __nv_bfloat162* wp =
                (const __nv_bfloat162*)(Wt2h + (kr0 + k4 + q) * W2LD + d0);
            float2 wa = __bfloat1622float2(wp[0]);
            float2 wb = __bfloat1622float2(wp[1]);
#pragma unroll
            for (int bb = 0; bb < 2; bb++) {
                a4[bb][0] += hv[bb][q] * wa.x; a4[bb][1] += hv[bb][q] * wa.y;
                a4[bb][2] += hv[bb][q] * wb.x; a4[bb][3] += hv[bb][q] * wb.y;
            }
        }
    }

    if (wh == 1) {
#pragma unroll
        for (int bb = 0; bb < 2; bb++)
            *(float4*)(sgb + bL[bb] * 128 + d0) =
                make_float4(a4[bb][0], a4[bb][1], a4[bb][2], a4[bb][3]);
    }
    __syncthreads();

    if (wh == 0) {
#pragma unroll
        for (int bb = 0; bb < 2; bb++) {
            int bg = b0 + bL[bb];
            int xb = x_batch[bg];
            float4 sg4 = *(const float4*)(sgb + bL[bb] * 128 + d0);
            float4 ep4 = *(const float4*)(eps + (size_t)bg * DD + d0);
            float4 gs4 = *(const float4*)(gen_sigma_emb + (size_t)xb * DD + d0);
            float sgv[4] = {sg4.x, sg4.y, sg4.z, sg4.w};
            float epv[4] = {ep4.x, ep4.y, ep4.z, ep4.w};
            float gsv[4] = {gs4.x, gs4.y, gs4.z, gs4.w};
            float zq[4];
            float klacc = 0.f;
#pragma unroll
            for (int q = 0; q < 4; q++) {
                float m   = a4[bb][q];
                float isg = softplusf(sgv[q]);
                float zv  = m + epv[q] * isg;
                zq[q] = zv;
                float sgm = softplusf(gsv[q]);
                float dm  = m - sgm;
                klacc += logf(sgm / isg)
                       + (isg * isg + dm * dm) / (2.f * sgm * sgm) - 0.5f;
            }
            *(float4*)(zsm + bL[bb] * 128 + d0) = make_float4(zq[0], zq[1], zq[2], zq[3]);
            __nv_bfloat162 p0 = __floats2bfloat162_rn(zq[0], zq[1]);
            __nv_bfloat162 p1 = __floats2bfloat162_rn(zq[2], zq[3]);
            ((__nv_bfloat162*)(g_zb + (size_t)bg * DD + d0))[0] = p0;
            ((__nv_bfloat162*)(g_zb + (size_t)bg * DD + d0))[1] = p1;
#pragma unroll
            for (int o = 16; o; o >>= 1) klacc += __shfl_xor_sync(0xffffffffu, klacc, o);
            if (lane == 0) g_kl[bg] = klacc;
        }
    }
    __syncthreads();

    // ---- picked context logits: 10 pairs per warp, chunked 5+5 for LDG ILP ----
#pragma unroll
    for (int ch = 0; ch < 2; ch++) {
        int nn[5], bq[5];
        float bgv[5];
#pragma unroll
        for (int u = 0; u < 5; u++) {
            int pp = w + (ch * 5 + u) * 16;
            bq[u] = pp / CC;
            nn[u] = ctx[(b0 + bq[u]) * CC + (pp - bq[u] * CC)];
        }
        float4 wv[5], zv[5];
#pragma unroll
        for (int u = 0; u < 5; u++) {
            wv[u]  = ((const float4*)(W_gen + (size_t)nn[u] * DD))[lane];
            zv[u]  = *(const float4*)(zsm + bq[u] * 128 + d0);
            bgv[u] = b_gen[nn[u]];
        }
#pragma unroll
        for (int u = 0; u < 5; u++) {
            float d = zv[u].x * wv[u].x + zv[u].y * wv[u].y
                    + zv[u].z * wv[u].z + zv[u].w * wv[u].w;
#pragma unroll
            for (int o = 16; o; o >>= 1) d += __shfl_xor_sync(0xffffffffu, d, o);
            if (lane == 0) atomicAdd(&g_R[b0 + bq[u]], d + bgv[u]);
        }
    }
}

// ---------------- kernel 2: bf16 mma GEMM + exp-rowsum ----------------
#define MT_PER_CTA 8
#define CP_ASYNC16(dst, src) \
    asm volatile("cp.async.cg.shared.global [%0], [%1], 16;" :: "r"(dst), "l"(src))
#define CP_COMMIT()  asm volatile("cp.async.commit_group;" ::: "memory")
#define CP_WAIT(n)   asm volatile("cp.async.wait_group %0;" :: "n"(n) : "memory")

#define TLD    136
#define FB_WS  69632
#define FB_BG  104448
#define SMEM_LOG 104960

__device__ __forceinline__ void fb_prefetch(uint32_t sb, int mt, int p, int tid) {
#pragma unroll
    for (int idx = tid; idx < 2048; idx += 256) {
        int r = idx >> 4, c = idx & 15;
        uint32_t dst = sb + (uint32_t)(p * 34816 + (r * TLD + c * 8) * 2);
        const void* src = (const void*)(g_zb + (size_t)(mt * 128 + r) * DD + c * 8);
        CP_ASYNC16(dst, src);
    }
    CP_COMMIT();
}

__global__ void __launch_bounds__(256, 2) k_logits(const float* __restrict__ W_gen,
                                                   const float* __restrict__ b_gen) {
    extern __shared__ __align__(16) char smem[];
    const uint32_t sb = smem_to_u32(smem);
    __nv_bfloat16* Ws = (__nv_bfloat16*)(smem + FB_WS);
    float* bg_s = (float*)(smem + FB_BG);

    const int tid = threadIdx.x;
    const int n0  = blockIdx.x * 128;
    const int mt0 = blockIdx.y * MT_PER_CTA;

    // first A-tile loads overlap the W fp32->bf16 conversion below
    fb_prefetch(sb, mt0, 0, tid);

    for (int gidx = tid; gidx < 2048; gidx += 256) {
        int r = gidx >> 4, c = gidx & 15;
        int n = n0 + r;
        uint4 outv = make_uint4(0u, 0u, 0u, 0u);
        if (n < NV) {
            const float4* src = (const float4*)(W_gen + (size_t)n * DD + c * 8);
            outv = f8_to_bf16x8(src[0], src[1]);
        }
        *(uint4*)(Ws + r * TLD + c * 8) = outv;
    }
    if (tid < 128) {
        int n = n0 + tid;
        bg_s[tid] = (n < NV) ? b_gen[n] : -88.0f;
    }

    const int w    = tid >> 5;
    const int lane = tid & 31;
    const int g    = lane >> 2;
    const int t    = lane & 3;
    const int wm   = w & 3;
    const int wn   = w >> 2;

    const uint32_t aLane = (uint32_t)(((wm * 32 + (lane & 15)) * TLD + ((lane & 16) >> 1)) * 2);
    uint32_t bAddr[4];
#pragma unroll
    for (int jp = 0; jp < 4; jp++)
        bAddr[jp] = sb + FB_WS +
            (uint32_t)(((wn * 64 + jp * 16 + ((lane & 16) >> 1) + (lane & 7)) * TLD + (lane & 8)) * 2);

    for (int lt = 0; lt < MT_PER_CTA; lt++) {
        const int p = lt & 1;
        if (lt + 1 < MT_PER_CTA) { fb_prefetch(sb, mt0 + lt + 1, p ^ 1, tid); CP_WAIT(1); }
        else                     { CP_WAIT(0); }
        __syncthreads();
        const uint32_t aBase0 = sb + (uint32_t)(p * 34816) + aLane;
        const uint32_t aBase1 = aBase0 + (uint32_t)(16 * TLD * 2);

        float acc[2][8][4];
#pragma unroll
        for (int i = 0; i < 2; i++)
#pragma unroll
            for (int j = 0; j < 8; j++)
#pragma unroll
                for (int q = 0; q < 4; q++) acc[i][j][q] = 0.f;

#pragma unroll
        for (int kk = 0; kk < 8; kk++) {
            const uint32_t kb = (uint32_t)(kk * 32);
            uint32_t a0[4], a1[4];
            ldmatrix_x4(a0, aBase0 + kb);
            ldmatrix_x4(a1, aBase1 + kb);
#pragma unroll
            for (int jp = 0; jp < 4; jp++) {
                uint32_t bq[4];
                ldmatrix_x4(bq, bAddr[jp] + kb);
                mma16816(acc[0][2 * jp],     a0, bq[0], bq[1]);
                mma16816(acc[1][2 * jp],     a1, bq[0], bq[1]);
                mma16816(acc[0][2 * jp + 1], a0, bq[2], bq[3]);
                mma16816(acc[1][2 * jp + 1], a1, bq[2], bq[3]);
            }
        }

        const int mt = mt0 + lt;
#pragma unroll
        for (int i = 0; i < 2; i++) {
            float rs0 = 0.f, rs1 = 0.f;
#pragma unroll
            for (int j = 0; j < 8; j++) {
                int nl = wn * 64 + j * 8 + 2 * t;
                float bg0 = bg_s[nl], bg1 = bg_s[nl + 1];
                rs0 += __expf(acc[i][j][0] + bg0) + __expf(acc[i][j][1] + bg1);
                rs1 += __expf(acc[i][j][2] + bg0) + __expf(acc[i][j][3] + bg1);
            }
            rs0 += __shfl_xor_sync(0xffffffffu, rs0, 1);
            rs0 += __shfl_xor_sync(0xffffffffu, rs0, 2);
            rs1 += __shfl_xor_sync(0xffffffffu, rs1, 1);
            rs1 += __shfl_xor_sync(0xffffffffu, rs1, 2);
            if (t == 0) {
                int m = mt * 128 + wm * 32 + i * 16 + g;
                atomicAdd(&g_S[m], rs0);
                atomicAdd(&g_S[m + 8], rs1);
            }
        }
        __syncthreads();
    }
}

// ---------------- kernel 3: final reduction ----------------
__global__ void __launch_bounds__(1024) k_final(float* __restrict__ out) {
    __shared__ float red[1024];
    const int tid = threadIdx.x;
    float a = 0.f;
    for (int i = tid; i < BB_; i += 1024)
        a += g_kl[i] - g_R[i] + (float)CC * __logf(g_S[i]);
    red[tid] = a;
    __syncthreads();
    for (int s = 512; s; s >>= 1) {
        if (tid < s) red[tid] += red[tid + s];
        __syncthreads();
    }
    if (tid == 0) out[0] = red[0] / (float)BB_;
}

// ---------------- launch ----------------
extern "C" void kernel_launch(void* const* d_in, const int* in_sizes, int n_in,
                              void* d_out, int out_size) {
    const int*   x_batch = (const int*)  d_in[0];
    const int*   ctx     = (const int*)  d_in[1];
    const float* eps     = (const float*)d_in[2];
    const float* inf_emb = (const float*)d_in[3];
    const float* W_aff   = (const float*)d_in[4];
    const float* b_aff   = (const float*)d_in[5];
    const float* W_mu    = (const float*)d_in[6];
    const float* b_mu    = (const float*)d_in[7];
    const float* W_sig   = (const float*)d_in[8];
    const float* b_sig   = (const float*)d_in[9];
    const float* gse     = (const float*)d_in[10];
    const float* W_gen   = (const float*)d_in[11];
    const float* b_gen   = (const float*)d_in[12];

    cudaFuncSetAttribute(k_infnet, cudaFuncAttributeMaxDynamicSharedMemorySize, SMEM_INF);
    cudaFuncSetAttribute(k_logits, cudaFuncAttributeMaxDynamicSharedMemorySize, SMEM_LOG);

    k_infnet<<<128, 512, SMEM_INF>>>(x_batch, ctx, eps, inf_emb, W_aff, b_aff,
                                     W_mu, b_mu, W_sig, b_sig, gse, W_gen, b_gen);
    k_logits<<<dim3(NPAD / 128, 2), 256, SMEM_LOG>>>(W_gen, b_gen);
    k_final<<<1, 1024>>>((float*)d_out);
}

// round 15
// speedup vs baseline: 1.0466x; 1.0466x over previous
#include <cuda_runtime.h>
#include <cuda_bf16.h>
#include <math.h>
#include <stdint.h>

#define NV   50257
#define NPAD 50304          // 393 * 128
#define NT   (NPAD / 128)   // 393 vocab tiles
#define DD   128
#define BB_  2048
#define CC   10
#define NITEMS (NT * 16)    // 6288 (vocab-tile, batch-tile) work items
#define LOG_GRID 296        // 148 SMs x 2 CTA/SM = one resident wave

typedef unsigned long long u64;

// ---------------- scratch (static __device__ — allocation-free) ----------------
__device__ __align__(16) __nv_bfloat16 g_zb[BB_ * DD];    // z in bf16
__device__ float g_S[BB_];                                // sum exp(logits) per row
__device__ float g_R[BB_];                                // sum of picked logits per row
__device__ float g_kl[BB_];

// ---------------- common helpers ----------------
__device__ __forceinline__ uint32_t smem_to_u32(const void* p) {
    uint32_t a;
    asm("{ .reg .u64 t; cvta.to.shared.u64 t, %1; cvt.u32.u64 %0, t; }"
        : "=r"(a) : "l"(p));
    return a;
}
__device__ __forceinline__ float softplusf(float x) {
    return fmaxf(x, 0.f) + log1pf(expf(-fabsf(x)));
}
__device__ __forceinline__ void mma16816(float c[4], const uint32_t a[4],
                                         uint32_t b0, uint32_t b1) {
    asm volatile(
        "mma.sync.aligned.m16n8k16.row.col.f32.bf16.bf16.f32 "
        "{%0,%1,%2,%3},{%4,%5,%6,%7},{%8,%9},{%0,%1,%2,%3};\n"
        : "+f"(c[0]), "+f"(c[1]), "+f"(c[2]), "+f"(c[3])
        : "r"(a[0]), "r"(a[1]), "r"(a[2]), "r"(a[3]), "r"(b0), "r"(b1));
}
__device__ __forceinline__ void ldmatrix_x4(uint32_t r[4], uint32_t addr) {
    asm volatile("ldmatrix.sync.aligned.m8n8.x4.shared.b16 {%0,%1,%2,%3}, [%4];"
        : "=r"(r[0]), "=r"(r[1]), "=r"(r[2]), "=r"(r[3]) : "r"(addr));
}
__device__ __forceinline__ uint4 f8_to_bf16x8(float4 f0, float4 f1) {
    __nv_bfloat162 h0 = __floats2bfloat162_rn(f0.x, f0.y);
    __nv_bfloat162 h1 = __floats2bfloat162_rn(f0.z, f0.w);
    __nv_bfloat162 h2 = __floats2bfloat162_rn(f1.x, f1.y);
    __nv_bfloat162 h3 = __floats2bfloat162_rn(f1.z, f1.w);
    return make_uint4(*(uint32_t*)&h0, *(uint32_t*)&h1,
                      *(uint32_t*)&h2, *(uint32_t*)&h3);
}

// ---------------- kernel 1: inference net (unchanged from round 13) ----------------
#define ALD   264
#define BLD   264
#define HLD   136
#define W2LD  136
#define OFF_A 0
#define OFF_B 101376
#define OFF_H 168960
#define SMEM_INF 221184
#define OFF_HS 135168
#define OFF_SG 143360
#define OFF_Z  151552

__global__ void __launch_bounds__(512) k_infnet(
    const int* __restrict__ x_batch, const int* __restrict__ ctx,
    const float* __restrict__ eps, const float* __restrict__ inf_emb,
    const float* __restrict__ W_aff, const float* __restrict__ b_aff,
    const float* __restrict__ W_mu,  const float* __restrict__ b_mu,
    const float* __restrict__ W_sig, const float* __restrict__ b_sig,
    const float* __restrict__ gen_sigma_emb,
    const float* __restrict__ W_gen, const float* __restrict__ b_gen)
{
    extern __shared__ __align__(16) char smx[];
    __nv_bfloat16* A  = (__nv_bfloat16*)(smx + OFF_A);
    __nv_bfloat16* Bm = (__nv_bfloat16*)(smx + OFF_B);
    __nv_bfloat16* H  = (__nv_bfloat16*)(smx + OFF_H);
    const uint32_t sb = smem_to_u32(smx);

    const int tid  = threadIdx.x;
    const int w    = tid >> 5;
    const int lane = tid & 31;
    const int b0   = blockIdx.x * 16;

    if (tid < 16) { g_S[b0 + tid] = 0.f; g_R[b0 + tid] = 0.f; }

    const uint4 z4 = make_uint4(0u, 0u, 0u, 0u);

    for (int idx = tid; idx < 128 * 32; idx += 512) {
        int d = idx >> 5, g8 = idx & 31;
        const float4* src = (const float4*)(W_aff + (size_t)d * 256 + g8 * 8);
        *(uint4*)(Bm + d * BLD + g8 * 8) = f8_to_bf16x8(src[0], src[1]);
    }
    if (tid < 128) *(uint4*)(Bm + tid * BLD + 256) = z4;

    for (int idx = tid; idx < 5120; idx += 512) {
        int r = idx >> 5, g8 = idx & 31;
        int b = r / 10, c = r - b * 10;
        int bg = b0 + b;
        int word = (g8 < 16) ? x_batch[bg] : ctx[bg * CC + c];
        const float4* src = (const float4*)(inf_emb + (size_t)word * DD + (g8 & 15) * 8);
        *(uint4*)(A + r * ALD + g8 * 8) = f8_to_bf16x8(src[0], src[1]);
    }
    if (tid < 160) *(uint4*)(A + tid * ALD + 256) = z4;
    for (int idx = tid; idx < 32 * 33; idx += 512) {
        int r = 160 + idx / 33, gc = idx % 33;
        *(uint4*)(A + r * ALD + gc * 8) = z4;
    }
    __syncthreads();

    const int wm = w & 3, wn = w >> 2;
    const uint32_t aBase = sb + OFF_A +
        (uint32_t)(((wm * 48 + (lane & 15)) * ALD + ((lane & 16) >> 1)) * 2);
    uint32_t bB[2];
#pragma unroll
    for (int np = 0; np < 2; np++)
        bB[np] = sb + OFF_B +
            (uint32_t)(((wn * 32 + np * 16 + ((lane & 16) >> 1) + (lane & 7)) * BLD
                        + (lane & 8)) * 2);

    float acc[3][4][4];
#pragma unroll
    for (int mi = 0; mi < 3; mi++)
#pragma unroll
        for (int nj = 0; nj < 4; nj++)
#pragma unroll
            for (int q = 0; q < 4; q++) acc[mi][nj][q] = 0.f;

#pragma unroll 4
    for (int kk = 0; kk < 16; kk++) {
        const uint32_t kb = (uint32_t)(kk * 32);
        uint32_t am[3][4];
#pragma unroll
        for (int mi = 0; mi < 3; mi++)
            ldmatrix_x4(am[mi], aBase + (uint32_t)(mi * 16 * ALD * 2) + kb);
#pragma unroll
        for (int np = 0; np < 2; np++) {
            uint32_t bq[4];
            ldmatrix_x4(bq, bB[np] + kb);
#pragma unroll
            for (int mi = 0; mi < 3; mi++) {
                mma16816(acc[mi][2 * np],     am[mi], bq[0], bq[1]);
                mma16816(acc[mi][2 * np + 1], am[mi], bq[2], bq[3]);
            }
        }
    }

    {
        const int g = lane >> 2, t = lane & 3;
        float2 bav[4];
#pragma unroll
        for (int nj = 0; nj < 4; nj++)
            bav[nj] = *(const float2*)(b_aff + wn * 32 + nj * 8 + 2 * t);
#pragma unroll
        for (int mi = 0; mi < 3; mi++) {
            int row = wm * 48 + mi * 16 + g;
#pragma unroll
            for (int nj = 0; nj < 4; nj++) {
                int col = wn * 32 + nj * 8 + 2 * t;
                float v0 = fmaxf(acc[mi][nj][0] + bav[nj].x, 0.f);
                float v1 = fmaxf(acc[mi][nj][1] + bav[nj].y, 0.f);
                float v2 = fmaxf(acc[mi][nj][2] + bav[nj].x, 0.f);
                float v3 = fmaxf(acc[mi][nj][3] + bav[nj].y, 0.f);
                *(__nv_bfloat162*)(H + row * HLD + col) = __floats2bfloat162_rn(v0, v1);
                *(__nv_bfloat162*)(H + (row + 8) * HLD + col) = __floats2bfloat162_rn(v2, v3);
            }
        }
    }
    __syncthreads();

    __nv_bfloat16* Wt2h = (__nv_bfloat16*)smx;
    float* hsm = (float*)(smx + OFF_HS);
    float* sgb = (float*)(smx + OFF_SG);
    float* zsm = (float*)(smx + OFF_Z);
    const int d0 = lane * 4;

    {
        int b = w;
        float s0 = 0.f, s1 = 0.f, s2 = 0.f, s3 = 0.f;
#pragma unroll
        for (int c = 0; c < CC; c++) {
            const __nv_bfloat162* hp = (const __nv_bfloat162*)(H + (b * 10 + c) * HLD + d0);
            float2 p0 = __bfloat1622float2(hp[0]);
            float2 p1 = __bfloat1622float2(hp[1]);
            s0 += p0.x; s1 += p0.y; s2 += p1.x; s3 += p1.y;
        }
        *(float4*)(hsm + b * 128 + d0) = make_float4(s0, s1, s2, s3);
    }
    for (int idx = tid; idx < 128 * 128; idx += 512) {
        int d = idx >> 7, k = idx & 127;
        Wt2h[k * W2LD + d]         = __float2bfloat16(W_mu[idx]);
        Wt2h[(128 + k) * W2LD + d] = __float2bfloat16(W_sig[idx]);
    }
    __syncthreads();

    const int wh = w >> 3, wq = w & 7;
    int bL[2] = {wq, wq + 8};
    float4 bias4 = wh ? *(const float4*)(b_sig + d0) : *(const float4*)(b_mu + d0);
    float a4[2][4];
#pragma unroll
    for (int bb = 0; bb < 2; bb++) {
        a4[bb][0] = bias4.x; a4[bb][1] = bias4.y;
        a4[bb][2] = bias4.z; a4[bb][3] = bias4.w;
    }
    const int kr0 = wh * 128;
    for (int k4 = 0; k4 < 128; k4 += 4) {
        float hv[2][4];
#pragma unroll
        for (int bb = 0; bb < 2; bb++)
            *(float4*)hv[bb] = *(const float4*)(hsm + bL[bb] * 128 + k4);
#pragma unroll
        for (int q = 0; q < 4; q++) {
            const __nv_bfloat162* wp =
                (const __nv_bfloat162*)(Wt2h + (kr0 + k4 + q) * W2LD + d0);
            float2 wa = __bfloat1622float2(wp[0]);
            float2 wb = __bfloat1622float2(wp[1]);
#pragma unroll
            for (int bb = 0; bb < 2; bb++) {
                a4[bb][0] += hv[bb][q] * wa.x; a4[bb][1] += hv[bb][q] * wa.y;
                a4[bb][2] += hv[bb][q] * wb.x; a4[bb][3] += hv[bb][q] * wb.y;
            }
        }
    }

    if (wh == 1) {
#pragma unroll
        for (int bb = 0; bb < 2; bb++)
            *(float4*)(sgb + bL[bb] * 128 + d0) =
                make_float4(a4[bb][0], a4[bb][1], a4[bb][2], a4[bb][3]);
    }
    __syncthreads();

    if (wh == 0) {
#pragma unroll
        for (int bb = 0; bb < 2; bb++) {
            int bg = b0 + bL[bb];
            int xb = x_batch[bg];
            float4 sg4 = *(const float4*)(sgb + bL[bb] * 128 + d0);
            float4 ep4 = *(const float4*)(eps + (size_t)bg * DD + d0);
            float4 gs4 = *(const float4*)(gen_sigma_emb + (size_t)xb * DD + d0);
            float sgv[4] = {sg4.x, sg4.y, sg4.z, sg4.w};
            float epv[4] = {ep4.x, ep4.y, ep4.z, ep4.w};
            float gsv[4] = {gs4.x, gs4.y, gs4.z, gs4.w};
            float zq[4];
            float klacc = 0.f;
#pragma unroll
            for (int q = 0; q < 4; q++) {
                float m   = a4[bb][q];
                float isg = softplusf(sgv[q]);
                float zv  = m + epv[q] * isg;
                zq[q] = zv;
                float sgm = softplusf(gsv[q]);
                float dm  = m - sgm;
                klacc += logf(sgm / isg)
                       + (isg * isg + dm * dm) / (2.f * sgm * sgm) - 0.5f;
            }
            *(float4*)(zsm + bL[bb] * 128 + d0) = make_float4(zq[0], zq[1], zq[2], zq[3]);
            __nv_bfloat162 p0 = __floats2bfloat162_rn(zq[0], zq[1]);
            __nv_bfloat162 p1 = __floats2bfloat162_rn(zq[2], zq[3]);
            ((__nv_bfloat162*)(g_zb + (size_t)bg * DD + d0))[0] = p0;
            ((__nv_bfloat162*)(g_zb + (size_t)bg * DD + d0))[1] = p1;
#pragma unroll
            for (int o = 16; o; o >>= 1) klacc += __shfl_xor_sync(0xffffffffu, klacc, o);
            if (lane == 0) g_kl[bg] = klacc;
        }
    }
    __syncthreads();

#pragma unroll
    for (int ch = 0; ch < 2; ch++) {
        int nn[5], bq[5];
        float bgv[5];
#pragma unroll
        for (int u = 0; u < 5; u++) {
            int pp = w + (ch * 5 + u) * 16;
            bq[u] = pp / CC;
            nn[u] = ctx[(b0 + bq[u]) * CC + (pp - bq[u] * CC)];
        }
        float4 wv[5], zv[5];
#pragma unroll
        for (int u = 0; u < 5; u++) {
            wv[u]  = ((const float4*)(W_gen + (size_t)nn[u] * DD))[lane];
            zv[u]  = *(const float4*)(zsm + bq[u] * 128 + d0);
            bgv[u] = b_gen[nn[u]];
        }
#pragma unroll
        for (int u = 0; u < 5; u++) {
            float d = zv[u].x * wv[u].x + zv[u].y * wv[u].y
                    + zv[u].z * wv[u].z + zv[u].w * wv[u].w;
#pragma unroll
            for (int o = 16; o; o >>= 1) d += __shfl_xor_sync(0xffffffffu, d, o);
            if (lane == 0) atomicAdd(&g_R[b0 + bq[u]], d + bgv[u]);
        }
    }
}

// ---------------- kernel 2: bf16 mma GEMM, single-wave work-item loop ----------------
// 296 CTAs (one resident wave at 2 CTA/SM). Work item i = (v = i>>4, mt = i&15),
// contiguous blocks per CTA -> per-CTA item counts 21/22 (3.5% imbalance vs
// 12.5% with 2.66 waves). W tile re-staged only when v changes (~2-3x per CTA).
#define CP_ASYNC16(dst, src) \
    asm volatile("cp.async.cg.shared.global [%0], [%1], 16;" :: "r"(dst), "l"(src))
#define CP_COMMIT()  asm volatile("cp.async.commit_group;" ::: "memory")
#define CP_WAIT(n)   asm volatile("cp.async.wait_group %0;" :: "n"(n) : "memory")

#define TLD    136
#define FB_WS  69632
#define FB_BG  104448
#define SMEM_LOG 104960

__device__ __forceinline__ void fb_prefetch(uint32_t sb, int mt, int p, int tid) {
#pragma unroll
    for (int idx = tid; idx < 2048; idx += 256) {
        int r = idx >> 4, c = idx & 15;
        uint32_t dst = sb + (uint32_t)(p * 34816 + (r * TLD + c * 8) * 2);
        const void* src = (const void*)(g_zb + (size_t)(mt * 128 + r) * DD + c * 8);
        CP_ASYNC16(dst, src);
    }
    CP_COMMIT();
}

__global__ void __launch_bounds__(256, 2) k_logits(const float* __restrict__ W_gen,
                                                   const float* __restrict__ b_gen) {
    extern __shared__ __align__(16) char smem[];
    const uint32_t sb = smem_to_u32(smem);
    __nv_bfloat16* Ws = (__nv_bfloat16*)(smem + FB_WS);
    float* bg_s = (float*)(smem + FB_BG);

    const int tid   = threadIdx.x;
    const int start = (int)(((long long)NITEMS * blockIdx.x) / gridDim.x);
    const int end   = (int)(((long long)NITEMS * (blockIdx.x + 1)) / gridDim.x);
    if (start >= end) return;

    const int w    = tid >> 5;
    const int lane = tid & 31;
    const int g    = lane >> 2;
    const int t    = lane & 3;
    const int wm   = w & 3;
    const int wn   = w >> 2;

    const uint32_t aLane = (uint32_t)(((wm * 32 + (lane & 15)) * TLD + ((lane & 16) >> 1)) * 2);
    uint32_t bAddr[4];
#pragma unroll
    for (int jp = 0; jp < 4; jp++)
        bAddr[jp] = sb + FB_WS +
            (uint32_t)(((wn * 64 + jp * 16 + ((lane & 16) >> 1) + (lane & 7)) * TLD + (lane & 8)) * 2);

    // prefetch first item's z tile; overlaps first W staging
    fb_prefetch(sb, start & 15, 0, tid);

    int curv = -1;
    for (int it = start; it < end; it++) {
        const int v  = it >> 4;
        const int mt = it & 15;
        const int p  = (it - start) & 1;

        if (it + 1 < end) { fb_prefetch(sb, (it + 1) & 15, p ^ 1, tid); CP_WAIT(1); }
        else              { CP_WAIT(0); }

        if (v != curv) {
            // previous item's compute finished at its trailing __syncthreads()
            const int n0 = v * 128;
            for (int gidx = tid; gidx < 2048; gidx += 256) {
                int r = gidx >> 4, c = gidx & 15;
                int n = n0 + r;
                uint4 outv = make_uint4(0u, 0u, 0u, 0u);
                if (n < NV) {
                    const float4* src = (const float4*)(W_gen + (size_t)n * DD + c * 8);
                    outv = f8_to_bf16x8(src[0], src[1]);
                }
                *(uint4*)(Ws + r * TLD + c * 8) = outv;
            }
            if (tid < 128) {
                int n = n0 + tid;
                bg_s[tid] = (n < NV) ? b_gen[n] : -88.0f;
            }
            curv = v;
        }
        __syncthreads();

        const uint32_t aBase0 = sb + (uint32_t)(p * 34816) + aLane;
        const uint32_t aBase1 = aBase0 + (uint32_t)(16 * TLD * 2);

        float acc[2][8][4];
#pragma unroll
        for (int i = 0; i < 2; i++)
#pragma unroll
            for (int j = 0; j < 8; j++)
#pragma unroll
                for (int q = 0; q < 4; q++) acc[i][j][q] = 0.f;

#pragma unroll
        for (int kk = 0; kk < 8; kk++) {
            const uint32_t kb = (uint32_t)(kk * 32);
            uint32_t a0[4], a1[4];
            ldmatrix_x4(a0, aBase0 + kb);
            ldmatrix_x4(a1, aBase1 + kb);
#pragma unroll
            for (int jp = 0; jp < 4; jp++) {
                uint32_t bq[4];
                ldmatrix_x4(bq, bAddr[jp] + kb);
                mma16816(acc[0][2 * jp],     a0, bq[0], bq[1]);
                mma16816(acc[1][2 * jp],     a1, bq[0], bq[1]);
                mma16816(acc[0][2 * jp + 1], a0, bq[2], bq[3]);
                mma16816(acc[1][2 * jp + 1], a1, bq[2], bq[3]);
            }
        }

#pragma unroll
        for (int i = 0; i < 2; i++) {
            float rs0 = 0.f, rs1 = 0.f;
#pragma unroll
            for (int j = 0; j < 8; j++) {
                int nl = wn * 64 + j * 8 + 2 * t;
                float bg0 = bg_s[nl], bg1 = bg_s[nl + 1];
                rs0 += __expf(acc[i][j][0] + bg0) + __expf(acc[i][j][1] + bg1);
                rs1 += __expf(acc[i][j][2] + bg0) + __expf(acc[i][j][3] + bg1);
            }
            rs0 += __shfl_xor_sync(0xffffffffu, rs0, 1);
            rs0 += __shfl_xor_sync(0xffffffffu, rs0, 2);
            rs1 += __shfl_xor_sync(0xffffffffu, rs1, 1);
            rs1 += __shfl_xor_sync(0xffffffffu, rs1, 2);
            if (t == 0) {
                int m = mt * 128 + wm * 32 + i * 16 + g;
                atomicAdd(&g_S[m], rs0);
                atomicAdd(&g_S[m + 8], rs1);
            }
        }
        __syncthreads();
    }
}

// ---------------- kernel 3: final reduction ----------------
__global__ void __launch_bounds__(1024) k_final(float* __restrict__ out) {
    __shared__ float red[1024];
    const int tid = threadIdx.x;
    float a = 0.f;
    for (int i = tid; i < BB_; i += 1024)
        a += g_kl[i] - g_R[i] + (float)CC * __logf(g_S[i]);
    red[tid] = a;
    __syncthreads();
    for (int s = 512; s; s >>= 1) {
        if (tid < s) red[tid] += red[tid + s];
        __syncthreads();
    }
    if (tid == 0) out[0] = red[0] / (float)BB_;
}

// ---------------- launch ----------------
extern "C" void kernel_launch(void* const* d_in, const int* in_sizes, int n_in,
                              void* d_out, int out_size) {
    const int*   x_batch = (const int*)  d_in[0];
    const int*   ctx     = (const int*)  d_in[1];
    const float* eps     = (const float*)d_in[2];
    const float* inf_emb = (const float*)d_in[3];
    const float* W_aff   = (const float*)d_in[4];
    const float* b_aff   = (const float*)d_in[5];
    const float* W_mu    = (const float*)d_in[6];
    const float* b_mu    = (const float*)d_in[7];
    const float* W_sig   = (const float*)d_in[8];
    const float* b_sig   = (const float*)d_in[9];
    const float* gse     = (const float*)d_in[10];
    const float* W_gen   = (const float*)d_in[11];
    const float* b_gen   = (const float*)d_in[12];

    cudaFuncSetAttribute(k_infnet, cudaFuncAttributeMaxDynamicSharedMemorySize, SMEM_INF);
    cudaFuncSetAttribute(k_logits, cudaFuncAttributeMaxDynamicSharedMemorySize, SMEM_LOG);

    k_infnet<<<128, 512, SMEM_INF>>>(x_batch, ctx, eps, inf_emb, W_aff, b_aff,
                                     W_mu, b_mu, W_sig, b_sig, gse, W_gen, b_gen);
    k_logits<<<LOG_GRID, 256, SMEM_LOG>>>(W_gen, b_gen);
    k_final<<<1, 1024>>>((float*)d_out);
}